// round 11
// baseline (speedup 1.0000x reference)
#include <cuda_runtime.h>
#include <math_constants.h>

// Fixed shapes
#define BB   8
#define NN   8192
#define SS   2048
#define SP   (SS / 2)      // 1024 point-pairs
#define DD   256
#define QB   64            // queries per block
#define TPB  256           // 4 threads per query (S split in quarters)
#define NPART 4
#define SPQ  (SP / NPART)  // 256 pairs per thread
#define EPSF 1e-8f

typedef unsigned long long u64;

__device__ __forceinline__ u64 f32x2_pack(float lo, float hi) {
    u64 r; asm("mov.b64 %0, {%1, %2};" : "=l"(r) : "f"(lo), "f"(hi)); return r;
}
__device__ __forceinline__ float2 f32x2_unpack(u64 v) {
    float2 r; asm("mov.b64 {%0, %1}, %2;" : "=f"(r.x), "=f"(r.y) : "l"(v)); return r;
}
__device__ __forceinline__ u64 fma_f32x2(u64 a, u64 b, u64 c) {
    u64 d; asm("fma.rn.f32x2 %0, %1, %2, %3;" : "=l"(d) : "l"(a), "l"(b), "l"(c)); return d;
}

// Insert (t,s) into ascending top-3 (d0<=d1<=d2). Strict '<' keeps earlier
// (lower-index) entries on ties, matching top_k's first-occurrence rule.
#define INSERT3(t, s)                                                   \
    if ((t) < d2) {                                                     \
        if ((t) < d1) {                                                 \
            d2 = d1; i2 = i1;                                           \
            if ((t) < d0) { d1 = d0; i1 = i0; d0 = (t); i0 = (s); }     \
            else          { d1 = (t); i1 = (s); }                       \
        } else { d2 = (t); i2 = (s); }                                  \
    }

__global__ __launch_bounds__(TPB)
void fp_interp_kernel(const float* __restrict__ xyz1,     // [B,3,N]
                      const float* __restrict__ xyz2,     // [B,3,S]
                      const float* __restrict__ points2,  // [B,S,D]
                      float* __restrict__ out)            // [B,N,D]
{
    // pair-interleaved source points: sA[sp]=(x0,x1,y0,y1), sB[sp]=(z0,z1,w0,w1)
    __shared__ ulonglong2 sA[SP];          // 16 KB
    __shared__ ulonglong2 sB[SP];          // 16 KB
    __shared__ float smd[NPART - 1][QB][3];
    __shared__ int   smi[NPART - 1][QB][3];
    __shared__ float swgt[QB][3];
    __shared__ int   sidx[QB][3];

    const int tile = blockIdx.x;           // 0..1023 (128 tiles per batch)
    const int b    = tile >> 7;
    const int n0   = (tile & 127) * QB;
    const int tid  = threadIdx.x;

    // --- stage xyz2[b] pair-interleaved with |p|^2 in w ---
    const float* x2b = xyz2 + (size_t)b * 3 * SS;
    #pragma unroll
    for (int sp = tid; sp < SP; sp += TPB) {
        const int s0 = 2 * sp;
        const float x0 = x2b[s0],          x1 = x2b[s0 + 1];
        const float y0 = x2b[SS + s0],     y1 = x2b[SS + s0 + 1];
        const float z0 = x2b[2 * SS + s0], z1 = x2b[2 * SS + s0 + 1];
        const float w0 = fmaf(x0, x0, fmaf(y0, y0, z0 * z0));
        const float w1 = fmaf(x1, x1, fmaf(y1, y1, z1 * z1));
        ((float4*)sA)[sp] = make_float4(x0, x1, y0, y1);
        ((float4*)sB)[sp] = make_float4(z0, z1, w0, w1);
    }
    __syncthreads();

    // --- phase 1: 4-way split top-3 scan; t = |p|^2 - 2 q.p (same order as d) ---
    const int q    = tid & (QB - 1);
    const int part = tid >> 6;             // 0..3 (uniform per warp)
    const int n    = n0 + q;
    const float* x1b = xyz1 + (size_t)b * 3 * NN;
    const float qx = x1b[n], qy = x1b[NN + n], qz = x1b[2 * NN + n];
    const float qq = fmaf(qx, qx, fmaf(qy, qy, qz * qz));
    const u64 ax2 = f32x2_pack(-2.0f * qx, -2.0f * qx);
    const u64 ay2 = f32x2_pack(-2.0f * qy, -2.0f * qy);
    const u64 az2 = f32x2_pack(-2.0f * qz, -2.0f * qz);

    float d0 = CUDART_MAX_NORMAL_F, d1 = CUDART_MAX_NORMAL_F, d2 = CUDART_MAX_NORMAL_F;
    int   i0 = 0, i1 = 0, i2 = 0;

    const int spbeg = part * SPQ;
    #pragma unroll 2
    for (int sp = spbeg; sp < spbeg + SPQ; sp += 2) {   // 2 pairs = 4 points/iter
        const ulonglong2 a0 = sA[sp];       // (x01, y01)
        const ulonglong2 b0 = sB[sp];       // (z01, w01)
        const ulonglong2 a1 = sA[sp + 1];
        const ulonglong2 b1 = sB[sp + 1];
        const u64 t01 = fma_f32x2(a0.x, ax2, fma_f32x2(a0.y, ay2, fma_f32x2(b0.x, az2, b0.y)));
        const u64 t23 = fma_f32x2(a1.x, ax2, fma_f32x2(a1.y, ay2, fma_f32x2(b1.x, az2, b1.y)));
        const float2 ta = f32x2_unpack(t01);
        const float2 tb = f32x2_unpack(t23);
        const float  m  = fminf(fminf(ta.x, ta.y), fminf(tb.x, tb.y));
        if (m < d2) {                       // rare
            const int s = 2 * sp;
            INSERT3(ta.x, s)
            INSERT3(ta.y, s + 1)
            INSERT3(tb.x, s + 2)
            INSERT3(tb.y, s + 3)
        }
    }

    // --- merge the 4 partial triples (parts 1..3 publish; part 0 merges) ---
    if (part) {
        smd[part - 1][q][0] = d0; smd[part - 1][q][1] = d1; smd[part - 1][q][2] = d2;
        smi[part - 1][q][0] = i0; smi[part - 1][q][1] = i1; smi[part - 1][q][2] = i2;
    }
    __syncthreads();
    if (!part) {
        #pragma unroll
        for (int p = 0; p < NPART - 1; ++p) {
            #pragma unroll
            for (int k = 0; k < 3; ++k) {
                const float t = smd[p][q][k];
                const int   s = smi[p][q][k];
                INSERT3(t, s)
            }
        }
        // true squared distances and inverse-distance weights
        const float r0 = 1.0f / ((d0 + qq) + EPSF);
        const float r1 = 1.0f / ((d1 + qq) + EPSF);
        const float r2 = 1.0f / ((d2 + qq) + EPSF);
        const float inv = 1.0f / (r0 + r1 + r2);
        sidx[q][0] = i0; sidx[q][1] = i1; sidx[q][2] = i2;
        swgt[q][0] = r0 * inv; swgt[q][1] = r1 * inv; swgt[q][2] = r2 * inv;
    }
    __syncthreads();

    // --- phase 2: cooperative gather + weighted sum, coalesced float4 ---
    const int warp = tid >> 5;
    const int lane = tid & 31;
    const float4* p2f = (const float4*)(points2 + (size_t)b * SS * DD); // rows of 64 float4
    float4* ob = (float4*)(out + ((size_t)b * NN + n0) * DD);

    #pragma unroll
    for (int qi = warp; qi < QB; qi += TPB / 32) {
        const int j0 = sidx[qi][0] * (DD / 4);
        const int j1 = sidx[qi][1] * (DD / 4);
        const int j2 = sidx[qi][2] * (DD / 4);
        const float w0 = swgt[qi][0];
        const float w1 = swgt[qi][1];
        const float w2 = swgt[qi][2];
        float4* oq = ob + (size_t)qi * (DD / 4);
        #pragma unroll
        for (int j = lane; j < DD / 4; j += 32) {
            const float4 a = p2f[j0 + j];
            const float4 c = p2f[j1 + j];
            const float4 e = p2f[j2 + j];
            float4 r;
            r.x = w0 * a.x + w1 * c.x + w2 * e.x;
            r.y = w0 * a.y + w1 * c.y + w2 * e.y;
            r.z = w0 * a.z + w1 * c.z + w2 * e.z;
            r.w = w0 * a.w + w1 * c.w + w2 * e.w;
            oq[j] = r;
        }
    }
}

extern "C" void kernel_launch(void* const* d_in, const int* in_sizes, int n_in,
                              void* d_out, int out_size)
{
    // inputs: xyz1 [B,3,N], xyz2 [B,3,S], points1 [B,D,N] (unused), points2 [B,S,D]
    const float* xyz1    = (const float*)d_in[0];
    const float* xyz2    = (const float*)d_in[1];
    const float* points2 = (const float*)d_in[3];
    float* out = (float*)d_out;

    const int blocks = BB * (NN / QB);   // 8 * 128 = 1024
    fp_interp_kernel<<<blocks, TPB>>>(xyz1, xyz2, points2, out);
}